// round 1
// baseline (speedup 1.0000x reference)
#include <cuda_runtime.h>
#include <cstdint>
#include <cstdio>

// ---------------------------------------------------------------------------
// SwinTransformerBlock  (B=16, H=W=64, C=512, two window types ws=8/16)
// Round 0: full fp32 implementation. GEMMs via 128x128x8 double-buffered
// SGEMM with fused epilogues; attention fused with analytic bias/mask and
// online softmax; depthwise conv with register reuse.
// ---------------------------------------------------------------------------

#define TOK    65536            // B*H*W
#define CFULL  512
#define CHALF  256
#define SEGQ   (TOK*CHALF)      // one of q/k/v

// ---- scratch (static device memory; no runtime allocation) ----
__device__ float g_h1[(size_t)TOK*CFULL];
__device__ float g_x2pre[(size_t)TOK*CFULL];
__device__ float g_x2[(size_t)TOK*CFULL];
__device__ float g_x3[(size_t)TOK*CFULL];
__device__ float g_h3[(size_t)TOK*CFULL];
__device__ float g_qkv[(size_t)3*SEGQ];
__device__ float g_attn[(size_t)SEGQ];
__device__ float g_hidden[(size_t)TOK*2048];
__device__ int   g_gidx0[TOK];
__device__ int   g_gidx1[TOK];

// ---------------------------------------------------------------------------
// gather/scatter index: token id (window-partition order of rolled image)
//   -> spatial row index b*4096 + h*64 + w  in the unrolled image
// ---------------------------------------------------------------------------
__global__ void gather_idx_kernel() {
    int g = blockIdx.x * blockDim.x + threadIdx.x;
    if (g >= TOK) return;
    {   // t=0: ws=8, ss=4, nW_side=8
        int wi = g >> 6, p = g & 63;
        int b = wi >> 6; int wrem = wi & 63;
        int win_h = wrem >> 3, win_w = wrem & 7;
        int ph = p >> 3, pw = p & 7;
        int h = (win_h * 8 + ph + 4) & 63;
        int w = (win_w * 8 + pw + 4) & 63;
        g_gidx0[g] = (b << 12) + (h << 6) + w;
    }
    {   // t=1: ws=16, ss=8, nW_side=4
        int wi = g >> 8, p = g & 255;
        int b = wi >> 4; int wrem = wi & 15;
        int win_h = wrem >> 2, win_w = wrem & 3;
        int ph = p >> 4, pw = p & 15;
        int h = (win_h * 16 + ph + 8) & 63;
        int w = (win_w * 16 + pw + 8) & 63;
        g_gidx1[g] = (b << 12) + (h << 6) + w;
    }
}

// ---------------------------------------------------------------------------
// LayerNorm over last dim 512, rows = 65536. 128 threads/row, float4.
// ---------------------------------------------------------------------------
__global__ __launch_bounds__(128)
void ln_kernel(const float* __restrict__ x, const float* __restrict__ gamma,
               const float* __restrict__ beta, float* __restrict__ y) {
    int row = blockIdx.x;
    int tid = threadIdx.x;
    const float4 v = *(const float4*)(x + (size_t)row * 512 + tid * 4);
    float s  = v.x + v.y + v.z + v.w;
    float s2 = v.x*v.x + v.y*v.y + v.z*v.z + v.w*v.w;
#pragma unroll
    for (int o = 16; o > 0; o >>= 1) {
        s  += __shfl_xor_sync(0xffffffffu, s,  o);
        s2 += __shfl_xor_sync(0xffffffffu, s2, o);
    }
    __shared__ float sh[8];
    int wid = tid >> 5, lid = tid & 31;
    if (lid == 0) { sh[wid] = s; sh[4 + wid] = s2; }
    __syncthreads();
    float ts  = sh[0] + sh[1] + sh[2] + sh[3];
    float ts2 = sh[4] + sh[5] + sh[6] + sh[7];
    float mu  = ts  * (1.f / 512.f);
    float var = ts2 * (1.f / 512.f) - mu * mu;
    float inv = rsqrtf(var + 1e-5f);
    const float4 gv = *(const float4*)(gamma + tid * 4);
    const float4 bv = *(const float4*)(beta  + tid * 4);
    float4 o;
    o.x = (v.x - mu) * inv * gv.x + bv.x;
    o.y = (v.y - mu) * inv * gv.y + bv.y;
    o.z = (v.z - mu) * inv * gv.z + bv.z;
    o.w = (v.w - mu) * inv * gv.w + bv.w;
    *(float4*)(y + (size_t)row * 512 + tid * 4) = o;
}

// ---------------------------------------------------------------------------
// gelu (tanh approximation, matches jax.nn.gelu default)
// ---------------------------------------------------------------------------
__device__ __forceinline__ float gelu_f(float v) {
    float z = 0.7978845608028654f * (v + 0.044715f * v * v * v);
    float e = __expf(2.f * z);
    float t = 1.f - 2.f / (e + 1.f);     // tanh(z), overflow-safe
    return 0.5f * v * (1.f + t);
}

// ---------------------------------------------------------------------------
// SGEMM: C(MxN) = A(MxK) * B(KxN) (+epilogue).  BM=BN=128, BK=8, 256 thr,
// 8x8 microtile, double-buffered smem.
// AMODE: 0 = A direct (row r at A + r*lda + a_off)
//        1 = A gathered (row r at A + gidx[r]*lda + a_off)
// EPI:   0 = +bias, scatter into q/k/v layout (nWB,NH,n,hd)
//        1 = +bias, scatter to spatial (gidx) + shortcut add  -> out
//        2 = +bias, gelu -> out[r*N+c]
//        3 = +bias, + aux[r*N+c] -> out[r*N+c]
// ---------------------------------------------------------------------------
template<int AMODE, int EPI>
__global__ __launch_bounds__(256, 2)
void sgemm_kernel(const float* __restrict__ A, int lda, int a_off,
                  const float* __restrict__ Bw, int N, int K,
                  const int* __restrict__ gidx, const float* __restrict__ bias,
                  float* __restrict__ out, const float* __restrict__ aux,
                  float* __restrict__ qkvb, int lnN, int chan_off) {
    __shared__ float As[2][8][128];
    __shared__ float Bs[2][8][128];
    int tid = threadIdx.x;
    int bm = blockIdx.y * 128, bn = blockIdx.x * 128;
    int arow = tid >> 1, acol = (tid & 1) * 4;
    int brow = tid >> 5, bcol = (tid & 31) * 4;

    const float* aptr;
    {
        int r = bm + arow;
        size_t rr = (AMODE == 1) ? (size_t)gidx[r] : (size_t)r;
        aptr = A + rr * (size_t)lda + a_off + acol;
    }
    const float* bptr = Bw + (size_t)brow * N + bn + bcol;

    float acc[8][8];
#pragma unroll
    for (int i = 0; i < 8; i++)
#pragma unroll
        for (int j = 0; j < 8; j++) acc[i][j] = 0.f;

    float4 av = *(const float4*)(aptr);
    float4 bv = *(const float4*)(bptr);
    As[0][acol + 0][arow] = av.x; As[0][acol + 1][arow] = av.y;
    As[0][acol + 2][arow] = av.z; As[0][acol + 3][arow] = av.w;
    *(float4*)&Bs[0][brow][bcol] = bv;
    __syncthreads();

    int ty = tid >> 4, tx = tid & 15;
    int ktot = K >> 3;
    int buf = 0;
    for (int kt = 0; kt < ktot; kt++) {
        if (kt + 1 < ktot) {
            av = *(const float4*)(aptr + (kt + 1) * 8);
            bv = *(const float4*)(bptr + (size_t)(kt + 1) * 8 * N);
        }
#pragma unroll
        for (int k = 0; k < 8; k++) {
            float ar[8], br[8];
            *(float4*)&ar[0] = *(const float4*)&As[buf][k][ty * 8];
            *(float4*)&ar[4] = *(const float4*)&As[buf][k][ty * 8 + 4];
            *(float4*)&br[0] = *(const float4*)&Bs[buf][k][tx * 8];
            *(float4*)&br[4] = *(const float4*)&Bs[buf][k][tx * 8 + 4];
#pragma unroll
            for (int i = 0; i < 8; i++)
#pragma unroll
                for (int j = 0; j < 8; j++) acc[i][j] += ar[i] * br[j];
        }
        if (kt + 1 < ktot) {
            int nb = buf ^ 1;
            As[nb][acol + 0][arow] = av.x; As[nb][acol + 1][arow] = av.y;
            As[nb][acol + 2][arow] = av.z; As[nb][acol + 3][arow] = av.w;
            *(float4*)&Bs[nb][brow][bcol] = bv;
            __syncthreads();
            buf = nb;
        }
    }

    int r0 = bm + ty * 8, c0 = bn + tx * 8;
    if (EPI == 0) {
        int nmask = (1 << lnN) - 1;
#pragma unroll
        for (int i = 0; i < 8; i++) {
            int r = r0 + i;
            int wi = r >> lnN;
            int p  = r & nmask;
#pragma unroll
            for (int j = 0; j < 8; j++) {
                int c = c0 + j;
                float v = acc[i][j] + bias[c];
                int s  = c >> 8;
                int hh = (c >> 5) & 7;
                int d  = c & 31;
                size_t dst = (size_t)s * SEGQ +
                             ((((size_t)(wi * 8 + hh)) << lnN) + p) * 32 + d;
                qkvb[dst] = v;
            }
        }
    } else if (EPI == 1) {
#pragma unroll
        for (int i = 0; i < 8; i++) {
            int r = r0 + i;
            size_t src = (size_t)gidx[r] * 512 + chan_off;
#pragma unroll
            for (int j = 0; j < 8; j++) {
                int c = c0 + j;
                float v = acc[i][j] + bias[c];
                out[src + c] = aux[src + c] + v;
            }
        }
    } else if (EPI == 2) {
#pragma unroll
        for (int i = 0; i < 8; i++) {
            size_t ro = (size_t)(r0 + i) * N;
#pragma unroll
            for (int j = 0; j < 8; j++)
                out[ro + c0 + j] = gelu_f(acc[i][j] + bias[c0 + j]);
        }
    } else {
#pragma unroll
        for (int i = 0; i < 8; i++) {
            size_t ro = (size_t)(r0 + i) * N;
#pragma unroll
            for (int j = 0; j < 8; j++) {
                float v = acc[i][j] + bias[c0 + j];
                out[ro + c0 + j] = v + aux[ro + c0 + j];
            }
        }
    }
}

// ---------------------------------------------------------------------------
// Windowed attention, one block per (window, head), one thread per query.
// Online softmax, K/V streamed through smem in chunks of <=128 keys.
// Relative-position bias and shift mask computed analytically.
// ---------------------------------------------------------------------------
__device__ __forceinline__ int region3(int i, int WS, int SS) {
    return (i < 64 - WS) ? 0 : ((i < 64 - SS) ? 1 : 2);
}

template<int WS, int SS>
__global__ void attn_kernel(const float* __restrict__ qkv,
                            const float* __restrict__ rpb,
                            float* __restrict__ outb) {
    constexpr int N  = WS * WS;
    constexpr int CH = (N > 128) ? 128 : N;
    constexpr int NWSIDE = 64 / WS;
    constexpr int NRPB = (2 * WS - 1) * (2 * WS - 1);
    __shared__ float Kc[CH][32];
    __shared__ float Vc[CH][32];
    __shared__ float rpbs[NRPB];

    int wi = blockIdx.x, hh = blockIdx.y;
    int q = threadIdx.x;
    size_t base = ((size_t)(wi * 8 + hh)) * N * 32;
    const float* Qp = qkv + base;
    const float* Kp = qkv + (size_t)SEGQ + base;
    const float* Vp = qkv + (size_t)2 * SEGQ + base;

    for (int i = q; i < NRPB; i += N) rpbs[i] = rpb[i * 8 + hh];

    float qreg[32];
#pragma unroll
    for (int d = 0; d < 32; d++)
        qreg[d] = Qp[q * 32 + d] * 0.17677669529663687f;   // 1/sqrt(32)

    int wrem = wi % (NWSIDE * NWSIDE);
    int win_h = wrem / NWSIDE, win_w = wrem % NWSIDE;
    int qh = q / WS, qw = q % WS;
    int region_q = region3(win_h * WS + qh, WS, SS) * 3 +
                   region3(win_w * WS + qw, WS, SS);

    float m = -1e30f, l = 0.f;
    float accv[32];
#pragma unroll
    for (int d = 0; d < 32; d++) accv[d] = 0.f;

    for (int c0 = 0; c0 < N; c0 += CH) {
        __syncthreads();
        for (int e = q; e < CH * 32; e += N) {
            ((float*)Kc)[e] = Kp[(size_t)c0 * 32 + e];
            ((float*)Vc)[e] = Vp[(size_t)c0 * 32 + e];
        }
        __syncthreads();
        for (int kk = 0; kk < CH; kk++) {
            int kidx = c0 + kk;
            float s = 0.f;
#pragma unroll
            for (int d = 0; d < 32; d++) s += qreg[d] * Kc[kk][d];
            int kh = kidx / WS, kw = kidx % WS;
            s += rpbs[(qh - kh + WS - 1) * (2 * WS - 1) + (qw - kw + WS - 1)];
            int region_k = region3(win_h * WS + kh, WS, SS) * 3 +
                           region3(win_w * WS + kw, WS, SS);
            if (region_k != region_q) s -= 100.f;
            if (s > m) {
                float corr = __expf(m - s);
                l *= corr;
#pragma unroll
                for (int d = 0; d < 32; d++) accv[d] *= corr;
                m = s;
            }
            float p = __expf(s - m);
            l += p;
#pragma unroll
            for (int d = 0; d < 32; d++) accv[d] += p * Vc[kk][d];
        }
    }
    float invl = 1.f / l;
    size_t ob = ((size_t)(wi * N + q)) * 256 + hh * 32;
#pragma unroll
    for (int d = 0; d < 32; d++) outb[ob + d] = accv[d] * invl;
}

// ---------------------------------------------------------------------------
// Depthwise conv (SAME, odd k) + residual: x3 = x2 + dwconv(x2) + b
// One block per (b, h, 4 consecutive w), 256 threads = channels of one type.
// ---------------------------------------------------------------------------
template<int KS>
__global__ __launch_bounds__(256)
void dwconv_kernel(const float* __restrict__ x2, const float* __restrict__ w,
                   const float* __restrict__ bias, float* __restrict__ x3,
                   int chan_off) {
    constexpr int PAD = KS / 2;
    int cc = threadIdx.x;
    int pos = blockIdx.x;               // 16 wgroups x 64 h x 16 b
    int wbase = (pos & 15) * 4;
    int h = (pos >> 4) & 63;
    int b = pos >> 10;
    float acc[4] = {0.f, 0.f, 0.f, 0.f};
    for (int dh = 0; dh < KS; dh++) {
        int ih = h + dh - PAD;
        if (ih < 0 || ih >= 64) continue;
        float xv[KS + 3];
#pragma unroll
        for (int j = 0; j < KS + 3; j++) {
            int iw = wbase + j - PAD;
            xv[j] = (iw >= 0 && iw < 64)
                ? x2[(((size_t)b * 64 + ih) * 64 + iw) * 512 + chan_off + cc]
                : 0.f;
        }
#pragma unroll
        for (int dw = 0; dw < KS; dw++) {
            float wt = w[(dh * KS + dw) * 256 + cc];
#pragma unroll
            for (int o = 0; o < 4; o++) acc[o] += xv[dw + o] * wt;
        }
    }
    float bb = bias[cc];
#pragma unroll
    for (int o = 0; o < 4; o++) {
        size_t idx = (((size_t)b * 64 + h) * 64 + (wbase + o)) * 512 + chan_off + cc;
        x3[idx] = x2[idx] + acc[o] + bb;
    }
}

// ---------------------------------------------------------------------------
// host driver
// ---------------------------------------------------------------------------
extern "C" void kernel_launch(void* const* d_in, const int* in_sizes, int n_in,
                              void* d_out, int out_size) {
    // inputs in setup_inputs insertion order
    const float* x       = (const float*)d_in[0];
    const float* g1      = (const float*)d_in[1];
    const float* g2      = (const float*)d_in[2];
    const float* g3      = (const float*)d_in[3];
    const float* beta1   = (const float*)d_in[4];
    const float* beta2   = (const float*)d_in[5];
    const float* beta3   = (const float*)d_in[6];
    const float* qkv_w0  = (const float*)d_in[7];
    const float* qkv_b0  = (const float*)d_in[8];
    const float* proj_w0 = (const float*)d_in[9];
    const float* proj_b0 = (const float*)d_in[10];
    const float* rpb0    = (const float*)d_in[11];
    const float* conv_w0 = (const float*)d_in[12];
    const float* conv_b0 = (const float*)d_in[13];
    const float* qkv_w1  = (const float*)d_in[14];
    const float* qkv_b1  = (const float*)d_in[15];
    const float* proj_w1 = (const float*)d_in[16];
    const float* proj_b1 = (const float*)d_in[17];
    const float* rpb1    = (const float*)d_in[18];
    const float* conv_w1 = (const float*)d_in[19];
    const float* conv_b1 = (const float*)d_in[20];
    const float* mlp_w1  = (const float*)d_in[21];
    const float* mlp_b1  = (const float*)d_in[22];
    const float* mlp_w2  = (const float*)d_in[23];
    const float* mlp_b2  = (const float*)d_in[24];
    float* out = (float*)d_out;

    float *h1, *x2pre, *x2, *x3, *h3, *qkv, *attn, *hidden;
    int *gi0, *gi1;
    cudaGetSymbolAddress((void**)&h1,     g_h1);
    cudaGetSymbolAddress((void**)&x2pre,  g_x2pre);
    cudaGetSymbolAddress((void**)&x2,     g_x2);
    cudaGetSymbolAddress((void**)&x3,     g_x3);
    cudaGetSymbolAddress((void**)&h3,     g_h3);
    cudaGetSymbolAddress((void**)&qkv,    g_qkv);
    cudaGetSymbolAddress((void**)&attn,   g_attn);
    cudaGetSymbolAddress((void**)&hidden, g_hidden);
    cudaGetSymbolAddress((void**)&gi0,    g_gidx0);
    cudaGetSymbolAddress((void**)&gi1,    g_gidx1);

    gather_idx_kernel<<<TOK / 256, 256>>>();

    // LN1
    ln_kernel<<<TOK, 128>>>(x, g1, beta1, h1);

    // ---- window type 0 (ws=8, ss=4) ----
    sgemm_kernel<1, 0><<<dim3(768 / 128, TOK / 128), 256>>>(
        h1, 512, 0, qkv_w0, 768, 256, gi0, qkv_b0,
        nullptr, nullptr, qkv, 6, 0);
    attn_kernel<8, 4><<<dim3(1024, 8), 64>>>(qkv, rpb0, attn);
    sgemm_kernel<0, 1><<<dim3(256 / 128, TOK / 128), 256>>>(
        attn, 256, 0, proj_w0, 256, 256, gi0, proj_b0,
        x2pre, x, nullptr, 0, 0);

    // ---- window type 1 (ws=16, ss=8) ----
    sgemm_kernel<1, 0><<<dim3(768 / 128, TOK / 128), 256>>>(
        h1, 512, 256, qkv_w1, 768, 256, gi1, qkv_b1,
        nullptr, nullptr, qkv, 8, 0);
    attn_kernel<16, 8><<<dim3(256, 8), 256>>>(qkv, rpb1, attn);
    sgemm_kernel<0, 1><<<dim3(256 / 128, TOK / 128), 256>>>(
        attn, 256, 0, proj_w1, 256, 256, gi1, proj_b1,
        x2pre, x, nullptr, 0, 256);

    // LN2
    ln_kernel<<<TOK, 128>>>(x2pre, g2, beta2, x2);

    // depthwise convs + residual
    dwconv_kernel<9><<<16384, 256>>>(x2, conv_w0, conv_b0, x3, 0);
    dwconv_kernel<17><<<16384, 256>>>(x2, conv_w1, conv_b1, x3, 256);

    // LN3
    ln_kernel<<<TOK, 128>>>(x3, g3, beta3, h3);

    // MLP
    sgemm_kernel<0, 2><<<dim3(2048 / 128, TOK / 128), 256>>>(
        h3, 512, 0, mlp_w1, 2048, 512, nullptr, mlp_b1,
        hidden, nullptr, nullptr, 0, 0);
    sgemm_kernel<0, 3><<<dim3(512 / 128, TOK / 128), 256>>>(
        hidden, 2048, 0, mlp_w2, 512, 2048, nullptr, mlp_b2,
        out, x3, nullptr, 0, 0);
}

// round 3
// speedup vs baseline: 1.8280x; 1.8280x over previous
#include <cuda_runtime.h>
#include <cstdint>

// ---------------------------------------------------------------------------
// SwinTransformerBlock  (B=16, H=W=64, C=512)
// Round 2: GEMMs via portable mma.sync tf32 (sm_100 baseline target has no
// tcgen05). 128x128xBK32 tiles, crossed-k swizzled smem, direct epilogues.
// ---------------------------------------------------------------------------

#define TOK    65536
#define SEGQ   (TOK*256)

// ---- scratch ----
__device__ float g_h1[(size_t)TOK*512];
__device__ float g_x2pre[(size_t)TOK*512];
__device__ float g_x2[(size_t)TOK*512];
__device__ float g_x3[(size_t)TOK*512];
__device__ float g_h3[(size_t)TOK*512];
__device__ float g_qkv[(size_t)3*SEGQ];
__device__ float g_attn[(size_t)SEGQ];
__device__ float g_hidden[(size_t)TOK*2048];
__device__ int   g_gidx0[TOK];
__device__ int   g_gidx1[TOK];
// transposed weights [N,K]
__device__ float g_qkvT0[768*256];
__device__ float g_qkvT1[768*256];
__device__ float g_projT0[256*256];
__device__ float g_projT1[256*256];
__device__ float g_mlp1T[2048*512];
__device__ float g_mlp2T[512*2048];

// ---------------------------------------------------------------------------
__device__ __forceinline__ uint32_t smem_u32(const void* p) {
    uint32_t a;
    asm("{ .reg .u64 t; cvta.to.shared.u64 t, %1; cvt.u32.u64 %0, t; }"
        : "=r"(a) : "l"(p));
    return a;
}
__device__ __forceinline__ uint32_t tf32r(float f) {
    uint32_t u;
    asm("cvt.rna.tf32.f32 %0, %1;" : "=r"(u) : "f"(f));
    return u;
}
__device__ __forceinline__ void sts32(uint32_t a, uint32_t v) {
    asm volatile("st.shared.b32 [%0], %1;" :: "r"(a), "r"(v) : "memory");
}
__device__ __forceinline__ uint2 lds64(uint32_t a) {
    uint2 r;
    asm volatile("ld.shared.v2.b32 {%0,%1}, [%2];" : "=r"(r.x), "=r"(r.y) : "r"(a));
    return r;
}
__device__ __forceinline__ void mma_tf32(float* c, uint2 alo, uint2 ahi, uint2 b) {
    // A regs order: a0=(g,tg) a1=(g+8,tg) a2=(g,tg+4) a3=(g+8,tg+4)
    asm volatile(
        "mma.sync.aligned.m16n8k8.row.col.f32.tf32.tf32.f32 "
        "{%0,%1,%2,%3}, {%4,%5,%6,%7}, {%8,%9}, {%0,%1,%2,%3};"
        : "+f"(c[0]), "+f"(c[1]), "+f"(c[2]), "+f"(c[3])
        : "r"(alo.x), "r"(ahi.x), "r"(alo.y), "r"(ahi.y), "r"(b.x), "r"(b.y));
}

__device__ __forceinline__ float gelu_f(float v) {
    float z = 0.7978845608028654f * (v + 0.044715f * v * v * v);
    float e = __expf(2.f * z);
    float t = 1.f - 2.f / (e + 1.f);
    return 0.5f * v * (1.f + t);
}

// ---------------------------------------------------------------------------
// gather/scatter index tables
// ---------------------------------------------------------------------------
__global__ void gather_idx_kernel() {
    int g = blockIdx.x * blockDim.x + threadIdx.x;
    if (g >= TOK) return;
    {   // t=0: ws=8, ss=4
        int wi = g >> 6, p = g & 63;
        int b = wi >> 6; int wrem = wi & 63;
        int h = ((wrem >> 3) * 8 + (p >> 3) + 4) & 63;
        int w = ((wrem & 7) * 8 + (p & 7) + 4) & 63;
        g_gidx0[g] = (b << 12) + (h << 6) + w;
    }
    {   // t=1: ws=16, ss=8
        int wi = g >> 8, p = g & 255;
        int b = wi >> 4; int wrem = wi & 15;
        int h = ((wrem >> 2) * 16 + (p >> 4) + 8) & 63;
        int w = ((wrem & 3) * 16 + (p & 15) + 8) & 63;
        g_gidx1[g] = (b << 12) + (h << 6) + w;
    }
}

// ---------------------------------------------------------------------------
// weight transpose [K,N] -> [N,K]
// ---------------------------------------------------------------------------
__global__ void transpose_kernel(const float* __restrict__ in,
                                 float* __restrict__ out, int K, int N) {
    __shared__ float t[32][33];
    int n0 = blockIdx.x * 32, k0 = blockIdx.y * 32;
    int x = threadIdx.x, y = threadIdx.y;
#pragma unroll
    for (int j = 0; j < 32; j += 8)
        t[y + j][x] = in[(size_t)(k0 + y + j) * N + n0 + x];
    __syncthreads();
#pragma unroll
    for (int j = 0; j < 32; j += 8)
        out[(size_t)(n0 + y + j) * K + k0 + x] = t[x][y + j];
}

// ---------------------------------------------------------------------------
// LayerNorm over last dim 512
// ---------------------------------------------------------------------------
__global__ __launch_bounds__(128)
void ln_kernel(const float* __restrict__ x, const float* __restrict__ gamma,
               const float* __restrict__ beta, float* __restrict__ y) {
    int row = blockIdx.x;
    int tid = threadIdx.x;
    const float4 v = *(const float4*)(x + (size_t)row * 512 + tid * 4);
    float s  = v.x + v.y + v.z + v.w;
    float s2 = v.x*v.x + v.y*v.y + v.z*v.z + v.w*v.w;
#pragma unroll
    for (int o = 16; o > 0; o >>= 1) {
        s  += __shfl_xor_sync(0xffffffffu, s,  o);
        s2 += __shfl_xor_sync(0xffffffffu, s2, o);
    }
    __shared__ float sh[8];
    int wid = tid >> 5, lid = tid & 31;
    if (lid == 0) { sh[wid] = s; sh[4 + wid] = s2; }
    __syncthreads();
    float ts  = sh[0] + sh[1] + sh[2] + sh[3];
    float ts2 = sh[4] + sh[5] + sh[6] + sh[7];
    float mu  = ts  * (1.f / 512.f);
    float var = ts2 * (1.f / 512.f) - mu * mu;
    float inv = rsqrtf(var + 1e-5f);
    const float4 gv = *(const float4*)(gamma + tid * 4);
    const float4 bv = *(const float4*)(beta  + tid * 4);
    float4 o;
    o.x = (v.x - mu) * inv * gv.x + bv.x;
    o.y = (v.y - mu) * inv * gv.y + bv.y;
    o.z = (v.z - mu) * inv * gv.z + bv.z;
    o.w = (v.w - mu) * inv * gv.w + bv.w;
    *(float4*)(y + (size_t)row * 512 + tid * 4) = o;
}

// ---------------------------------------------------------------------------
// mma.sync tf32 GEMM: 128x128 tile, BK=32, 256 thr (8 warps, 2M x 4N),
// warp tile 64x32, double-buffered smem with crossed-k swizzle.
//
// smem layout per tile (A or B, 128 rows x 32 k, fp32/tf32 words):
//   word(row, k) = row*32 + ((s ^ (row&3))*8) + kin*2 + kout
//   with s=k>>3, kin=(k&7)&3... i.e. k8=k&7: kin=k8&3, kout=k8>>2
// fragment load (row, kstep s): ld.v2 at row*32 + ((s^(row&3))*8) + tg*2
//   gives (k = s*8+tg, k = s*8+tg+4) -- exactly (a0,a2)/(a1,a3)/(b0,b1).
// ---------------------------------------------------------------------------
template<int AMODE, int EPI>
__global__ __launch_bounds__(256, 2)
void tc_gemm(const float* __restrict__ A, int lda, int a_off,
             const float* __restrict__ Bt, int N, int K,
             const int* __restrict__ gidx, const float* __restrict__ bias,
             float* __restrict__ out, const float* __restrict__ aux,
             float* __restrict__ qkvb, int lnN, int chan_off) {
    extern __shared__ __align__(16) char smraw[];
    const uint32_t sb = smem_u32(smraw);

    int tid = threadIdx.x;
    int lane = tid & 31, wid = tid >> 5;
    int wm = wid >> 2, wn = wid & 3;          // warp grid 2(M) x 4(N)
    int g = lane >> 2, tg = lane & 3;

    int bm = blockIdx.y * 128, bn = blockIdx.x * 128;

    // ---- global load setup (4 slots, each float4) ----
    const float* pA[4];
    const float* pB[4];
    uint32_t sts_off[4];
#pragma unroll
    for (int i = 0; i < 4; i++) {
        int slot = tid + i * 256;
        int r = slot >> 3, c4 = slot & 7;
        sts_off[i] = (uint32_t)(r * 32 + (((c4 >> 1) ^ (r & 3)) * 8) + (c4 & 1)) * 4;
        size_t ar = AMODE ? (size_t)__ldg(&gidx[bm + r]) : (size_t)(bm + r);
        pA[i] = A + ar * (size_t)lda + a_off + c4 * 4;
        pB[i] = Bt + (size_t)(bn + r) * K + c4 * 4;
    }

    // ---- fragment addresses ----
    uint32_t aoff[4][2], boff[4];
    uint32_t swz = (uint32_t)(g & 3);
#pragma unroll
    for (int i = 0; i < 4; i++) {
        int row = wm * 64 + i * 16 + g;
        aoff[i][0] = (uint32_t)(row * 32 + tg * 2) * 4;
        aoff[i][1] = (uint32_t)((row + 8) * 32 + tg * 2) * 4;
    }
#pragma unroll
    for (int j = 0; j < 4; j++) {
        int n = wn * 32 + j * 8 + g;
        boff[j] = (uint32_t)(n * 32 + tg * 2) * 4;
    }

    float acc[4][4][4];
#pragma unroll
    for (int i = 0; i < 4; i++)
#pragma unroll
        for (int j = 0; j < 4; j++)
#pragma unroll
            for (int e = 0; e < 4; e++) acc[i][j][e] = 0.f;

    const int S = K >> 5;

    // preload stage 0
    {
        uint32_t Ab = sb, Bb = sb + 16384;
#pragma unroll
        for (int i = 0; i < 4; i++) {
            float4 va = *(const float4*)pA[i];
            float4 vb = *(const float4*)pB[i];
            sts32(Ab + sts_off[i] + 0,  tf32r(va.x));
            sts32(Ab + sts_off[i] + 8,  tf32r(va.y));
            sts32(Ab + sts_off[i] + 16, tf32r(va.z));
            sts32(Ab + sts_off[i] + 24, tf32r(va.w));
            sts32(Bb + sts_off[i] + 0,  tf32r(vb.x));
            sts32(Bb + sts_off[i] + 8,  tf32r(vb.y));
            sts32(Bb + sts_off[i] + 16, tf32r(vb.z));
            sts32(Bb + sts_off[i] + 24, tf32r(vb.w));
        }
    }
    __syncthreads();

#pragma unroll 1
    for (int s = 0; s < S; s++) {
        float4 va[4], vb[4];
        if (s + 1 < S) {
#pragma unroll
            for (int i = 0; i < 4; i++) {
                va[i] = *(const float4*)(pA[i] + (s + 1) * 32);
                vb[i] = *(const float4*)(pB[i] + (s + 1) * 32);
            }
        }
        // compute current buffer
        uint32_t Ab = sb + (s & 1) * 32768, Bb = Ab + 16384;
#pragma unroll
        for (int s4 = 0; s4 < 4; s4++) {
            uint32_t ko = (uint32_t)((s4 ^ swz) * 32);
            uint2 af[4][2], bf[4];
#pragma unroll
            for (int i = 0; i < 4; i++) {
                af[i][0] = lds64(Ab + aoff[i][0] + ko);
                af[i][1] = lds64(Ab + aoff[i][1] + ko);
            }
#pragma unroll
            for (int j = 0; j < 4; j++) bf[j] = lds64(Bb + boff[j] + ko);
#pragma unroll
            for (int i = 0; i < 4; i++)
#pragma unroll
                for (int j = 0; j < 4; j++)
                    mma_tf32(acc[i][j], af[i][0], af[i][1], bf[j]);
        }
        if (s + 1 < S) {
            uint32_t An = sb + ((s + 1) & 1) * 32768, Bn = An + 16384;
#pragma unroll
            for (int i = 0; i < 4; i++) {
                sts32(An + sts_off[i] + 0,  tf32r(va[i].x));
                sts32(An + sts_off[i] + 8,  tf32r(va[i].y));
                sts32(An + sts_off[i] + 16, tf32r(va[i].z));
                sts32(An + sts_off[i] + 24, tf32r(va[i].w));
                sts32(Bn + sts_off[i] + 0,  tf32r(vb[i].x));
                sts32(Bn + sts_off[i] + 8,  tf32r(vb[i].y));
                sts32(Bn + sts_off[i] + 16, tf32r(vb[i].z));
                sts32(Bn + sts_off[i] + 24, tf32r(vb[i].w));
            }
            __syncthreads();
        }
    }

    // ---- epilogue: direct float2 stores ----
    int tc = tg;
#pragma unroll
    for (int i = 0; i < 4; i++) {
        int Rl = bm + wm * 64 + i * 16 + g;
        int Rh = Rl + 8;
        size_t rowl, rowh;
        if (EPI == 0) {
            int nmask = (1 << lnN) - 1;
            rowl = ((((size_t)((Rl >> lnN) * 8)) << lnN) + (Rl & nmask));
            rowh = ((((size_t)((Rh >> lnN) * 8)) << lnN) + (Rh & nmask));
        } else if (EPI == 1) {
            rowl = (size_t)__ldg(&gidx[Rl]) * 512 + chan_off;
            rowh = (size_t)__ldg(&gidx[Rh]) * 512 + chan_off;
        } else {
            rowl = (size_t)Rl * N;
            rowh = (size_t)Rh * N;
        }
#pragma unroll
        for (int j = 0; j < 4; j++) {
            int C = bn + wn * 32 + j * 8 + 2 * tc;
            float b0 = __ldg(&bias[C]), b1 = __ldg(&bias[C + 1]);
            float d0 = acc[i][j][0] + b0, d1 = acc[i][j][1] + b1;
            float d2 = acc[i][j][2] + b0, d3 = acc[i][j][3] + b1;
            if (EPI == 0) {
                int sseg = C >> 8, hh = (C >> 5) & 7, d = C & 31;
                size_t hoff = (size_t)sseg * SEGQ + ((size_t)hh << lnN) * 32 + d;
                float2* p0 = (float2*)(qkvb + hoff + rowl * 32);
                float2* p1 = (float2*)(qkvb + hoff + rowh * 32);
                *p0 = make_float2(d0, d1);
                *p1 = make_float2(d2, d3);
            } else if (EPI == 1) {
                const float2 a0 = *(const float2*)(aux + rowl + C);
                const float2 a1 = *(const float2*)(aux + rowh + C);
                *(float2*)(out + rowl + C) = make_float2(d0 + a0.x, d1 + a0.y);
                *(float2*)(out + rowh + C) = make_float2(d2 + a1.x, d3 + a1.y);
            } else if (EPI == 2) {
                *(float2*)(out + rowl + C) = make_float2(gelu_f(d0), gelu_f(d1));
                *(float2*)(out + rowh + C) = make_float2(gelu_f(d2), gelu_f(d3));
            } else {
                const float2 a0 = *(const float2*)(aux + rowl + C);
                const float2 a1 = *(const float2*)(aux + rowh + C);
                *(float2*)(out + rowl + C) = make_float2(d0 + a0.x, d1 + a0.y);
                *(float2*)(out + rowh + C) = make_float2(d2 + a1.x, d3 + a1.y);
            }
        }
    }
}

// ---------------------------------------------------------------------------
// windowed attention
// ---------------------------------------------------------------------------
__device__ __forceinline__ int region3(int i, int WS, int SS) {
    return (i < 64 - WS) ? 0 : ((i < 64 - SS) ? 1 : 2);
}

template<int WS, int SS>
__global__ void attn_kernel(const float* __restrict__ qkv,
                            const float* __restrict__ rpb,
                            float* __restrict__ outb) {
    constexpr int N  = WS * WS;
    constexpr int CH = (N > 128) ? 128 : N;
    constexpr int NWSIDE = 64 / WS;
    constexpr int NRPB = (2 * WS - 1) * (2 * WS - 1);
    __shared__ float Kc[CH][32];
    __shared__ float Vc[CH][32];
    __shared__ float rpbs[NRPB];

    int wi = blockIdx.x, hh = blockIdx.y;
    int q = threadIdx.x;
    size_t base = ((size_t)(wi * 8 + hh)) * N * 32;
    const float* Qp = qkv + base;
    const float* Kp = qkv + (size_t)SEGQ + base;
    const float* Vp = qkv + (size_t)2 * SEGQ + base;

    for (int i = q; i < NRPB; i += N) rpbs[i] = rpb[i * 8 + hh];

    float qreg[32];
#pragma unroll
    for (int d = 0; d < 32; d++)
        qreg[d] = Qp[q * 32 + d] * 0.17677669529663687f;

    int wrem = wi % (NWSIDE * NWSIDE);
    int win_h = wrem / NWSIDE, win_w = wrem % NWSIDE;
    int qh = q / WS, qw = q % WS;
    int region_q = region3(win_h * WS + qh, WS, SS) * 3 +
                   region3(win_w * WS + qw, WS, SS);

    float m = -1e30f, l = 0.f;
    float accv[32];
#pragma unroll
    for (int d = 0; d < 32; d++) accv[d] = 0.f;

    for (int c0 = 0; c0 < N; c0 += CH) {
        __syncthreads();
        for (int e = q; e < CH * 32; e += N) {
            ((float*)Kc)[e] = Kp[(size_t)c0 * 32 + e];
            ((float*)Vc)[e] = Vp[(size_t)c0 * 32 + e];
        }
        __syncthreads();
        for (int kk = 0; kk < CH; kk++) {
            int kidx = c0 + kk;
            float s = 0.f;
#pragma unroll
            for (int d = 0; d < 32; d++) s += qreg[d] * Kc[kk][d];
            int kh = kidx / WS, kw = kidx % WS;
            s += rpbs[(qh - kh + WS - 1) * (2 * WS - 1) + (qw - kw + WS - 1)];
            int region_k = region3(win_h * WS + kh, WS, SS) * 3 +
                           region3(win_w * WS + kw, WS, SS);
            if (region_k != region_q) s -= 100.f;
            if (s > m) {
                float corr = __expf(m - s);
                l *= corr;
#pragma unroll
                for (int d = 0; d < 32; d++) accv[d] *= corr;
                m = s;
            }
            float p = __expf(s - m);
            l += p;
#pragma unroll
            for (int d = 0; d < 32; d++) accv[d] += p * Vc[kk][d];
        }
    }
    float invl = 1.f / l;
    size_t ob = ((size_t)(wi * N + q)) * 256 + hh * 32;
#pragma unroll
    for (int d = 0; d < 32; d++) outb[ob + d] = accv[d] * invl;
}

// ---------------------------------------------------------------------------
// depthwise conv + residual
// ---------------------------------------------------------------------------
template<int KS>
__global__ __launch_bounds__(256)
void dwconv_kernel(const float* __restrict__ x2, const float* __restrict__ w,
                   const float* __restrict__ bias, float* __restrict__ x3,
                   int chan_off) {
    constexpr int PAD = KS / 2;
    int cc = threadIdx.x;
    int pos = blockIdx.x;
    int wbase = (pos & 15) * 4;
    int h = (pos >> 4) & 63;
    int b = pos >> 10;
    float acc[4] = {0.f, 0.f, 0.f, 0.f};
    for (int dh = 0; dh < KS; dh++) {
        int ih = h + dh - PAD;
        if (ih < 0 || ih >= 64) continue;
        float xv[KS + 3];
#pragma unroll
        for (int j = 0; j < KS + 3; j++) {
            int iw = wbase + j - PAD;
            xv[j] = (iw >= 0 && iw < 64)
                ? x2[(((size_t)b * 64 + ih) * 64 + iw) * 512 + chan_off + cc]
                : 0.f;
        }
#pragma unroll
        for (int dw = 0; dw < KS; dw++) {
            float wt = w[(dh * KS + dw) * 256 + cc];
#pragma unroll
            for (int o = 0; o < 4; o++) acc[o] += xv[dw + o] * wt;
        }
    }
    float bb = bias[cc];
#pragma unroll
    for (int o = 0; o < 4; o++) {
        size_t idx = (((size_t)b * 64 + h) * 64 + (wbase + o)) * 512 + chan_off + cc;
        x3[idx] = x2[idx] + acc[o] + bb;
    }
}

// ---------------------------------------------------------------------------
// host driver
// ---------------------------------------------------------------------------
#define GEMM_SMEM 65536

extern "C" void kernel_launch(void* const* d_in, const int* in_sizes, int n_in,
                              void* d_out, int out_size) {
    const float* x       = (const float*)d_in[0];
    const float* g1      = (const float*)d_in[1];
    const float* g2      = (const float*)d_in[2];
    const float* g3      = (const float*)d_in[3];
    const float* beta1   = (const float*)d_in[4];
    const float* beta2   = (const float*)d_in[5];
    const float* beta3   = (const float*)d_in[6];
    const float* qkv_w0  = (const float*)d_in[7];
    const float* qkv_b0  = (const float*)d_in[8];
    const float* proj_w0 = (const float*)d_in[9];
    const float* proj_b0 = (const float*)d_in[10];
    const float* rpb0    = (const float*)d_in[11];
    const float* conv_w0 = (const float*)d_in[12];
    const float* conv_b0 = (const float*)d_in[13];
    const float* qkv_w1  = (const float*)d_in[14];
    const float* qkv_b1  = (const float*)d_in[15];
    const float* proj_w1 = (const float*)d_in[16];
    const float* proj_b1 = (const float*)d_in[17];
    const float* rpb1    = (const float*)d_in[18];
    const float* conv_w1 = (const float*)d_in[19];
    const float* conv_b1 = (const float*)d_in[20];
    const float* mlp_w1  = (const float*)d_in[21];
    const float* mlp_b1  = (const float*)d_in[22];
    const float* mlp_w2  = (const float*)d_in[23];
    const float* mlp_b2  = (const float*)d_in[24];
    float* out = (float*)d_out;

    float *h1, *x2pre, *x2, *x3, *h3, *qkv, *attn, *hidden;
    float *qkvT0, *qkvT1, *projT0, *projT1, *mlp1T, *mlp2T;
    int *gi0, *gi1;
    cudaGetSymbolAddress((void**)&h1,     g_h1);
    cudaGetSymbolAddress((void**)&x2pre,  g_x2pre);
    cudaGetSymbolAddress((void**)&x2,     g_x2);
    cudaGetSymbolAddress((void**)&x3,     g_x3);
    cudaGetSymbolAddress((void**)&h3,     g_h3);
    cudaGetSymbolAddress((void**)&qkv,    g_qkv);
    cudaGetSymbolAddress((void**)&attn,   g_attn);
    cudaGetSymbolAddress((void**)&hidden, g_hidden);
    cudaGetSymbolAddress((void**)&gi0,    g_gidx0);
    cudaGetSymbolAddress((void**)&gi1,    g_gidx1);
    cudaGetSymbolAddress((void**)&qkvT0,  g_qkvT0);
    cudaGetSymbolAddress((void**)&qkvT1,  g_qkvT1);
    cudaGetSymbolAddress((void**)&projT0, g_projT0);
    cudaGetSymbolAddress((void**)&projT1, g_projT1);
    cudaGetSymbolAddress((void**)&mlp1T,  g_mlp1T);
    cudaGetSymbolAddress((void**)&mlp2T,  g_mlp2T);

    cudaFuncSetAttribute(tc_gemm<1, 0>, cudaFuncAttributeMaxDynamicSharedMemorySize, GEMM_SMEM);
    cudaFuncSetAttribute(tc_gemm<0, 1>, cudaFuncAttributeMaxDynamicSharedMemorySize, GEMM_SMEM);
    cudaFuncSetAttribute(tc_gemm<0, 2>, cudaFuncAttributeMaxDynamicSharedMemorySize, GEMM_SMEM);
    cudaFuncSetAttribute(tc_gemm<0, 3>, cudaFuncAttributeMaxDynamicSharedMemorySize, GEMM_SMEM);

    gather_idx_kernel<<<TOK / 256, 256>>>();
    transpose_kernel<<<dim3(24, 8),  dim3(32, 8)>>>(qkv_w0,  qkvT0, 256, 768);
    transpose_kernel<<<dim3(24, 8),  dim3(32, 8)>>>(qkv_w1,  qkvT1, 256, 768);
    transpose_kernel<<<dim3(8, 8),   dim3(32, 8)>>>(proj_w0, projT0, 256, 256);
    transpose_kernel<<<dim3(8, 8),   dim3(32, 8)>>>(proj_w1, projT1, 256, 256);
    transpose_kernel<<<dim3(64, 16), dim3(32, 8)>>>(mlp_w1,  mlp1T, 512, 2048);
    transpose_kernel<<<dim3(16, 64), dim3(32, 8)>>>(mlp_w2,  mlp2T, 2048, 512);

    ln_kernel<<<TOK, 128>>>(x, g1, beta1, h1);

    // window type 0 (ws=8, ss=4)
    tc_gemm<1, 0><<<dim3(6, 512), 256, GEMM_SMEM>>>(
        h1, 512, 0, qkvT0, 768, 256, gi0, qkv_b0, nullptr, nullptr, qkv, 6, 0);
    attn_kernel<8, 4><<<dim3(1024, 8), 64>>>(qkv, rpb0, attn);
    tc_gemm<0, 1><<<dim3(2, 512), 256, GEMM_SMEM>>>(
        attn, 256, 0, projT0, 256, 256, gi0, proj_b0, x2pre, x, nullptr, 0, 0);

    // window type 1 (ws=16, ss=8)
    tc_gemm<1, 0><<<dim3(6, 512), 256, GEMM_SMEM>>>(
        h1, 512, 256, qkvT1, 768, 256, gi1, qkv_b1, nullptr, nullptr, qkv, 8, 0);
    attn_kernel<16, 8><<<dim3(256, 8), 256>>>(qkv, rpb1, attn);
    tc_gemm<0, 1><<<dim3(2, 512), 256, GEMM_SMEM>>>(
        attn, 256, 0, projT1, 256, 256, gi1, proj_b1, x2pre, x, nullptr, 0, 256);

    ln_kernel<<<TOK, 128>>>(x2pre, g2, beta2, x2);

    dwconv_kernel<9><<<16384, 256>>>(x2, conv_w0, conv_b0, x3, 0);
    dwconv_kernel<17><<<16384, 256>>>(x2, conv_w1, conv_b1, x3, 256);

    ln_kernel<<<TOK, 128>>>(x3, g3, beta3, h3);

    tc_gemm<0, 2><<<dim3(16, 512), 256, GEMM_SMEM>>>(
        h3, 512, 0, mlp1T, 2048, 512, nullptr, mlp_b1, hidden, nullptr, nullptr, 0, 0);
    tc_gemm<0, 3><<<dim3(4, 512), 256, GEMM_SMEM>>>(
        hidden, 2048, 0, mlp2T, 512, 2048, nullptr, mlp_b2, out, x3, nullptr, 0, 0);
}